// round 14
// baseline (speedup 1.0000x reference)
#include <cuda_runtime.h>
#include <math.h>
#include <stdint.h>

#define NB   2
#define NC   256
#define NHW  2304     // 48*48
#define NCH  12

#define TI   32       // gray pixels per attention block (4 warps x 8 i)
#define TJC  32       // rgb pixels per smem tile
#define CH   128      // channel half per sub-tile (long phases: 32 c4-iters)
#define CSTR 132      // rn row stride (floats): v-lane bank stride 4 -> conflict-free
#define GSTR 260      // gn row stride (floats): i bank stride 4 -> conflict-free g-frag
#define CBUF (TJC*CSTR)           // floats per rn buffer (4224 = 16.9KB)
#define GX   7        // attention grid.x
#define JS   3        // j segments -> grid 462 blocks ~ 3.1/SM

#define ATTN_SMEM ((2*CBUF + TI*GSTR + 2*TJC*4)*4 + TI*4 + 16)

// ---------------- scratch ----------------
__device__ int    d_cls_g[NB * NHW];
__device__ int    d_cls_r[NB * NHW];
__device__ int    d_list_g[NB * NCH * NHW];
__device__ int    d_list_r[NB * NCH * NHW];
__device__ int    d_cnt_g[NB * NCH];
__device__ int    d_cnt_r[NB * NCH];
__device__ float  d_sum_g[NB * NCH * NC];
__device__ float  d_sum_r[NB * NCH * NC];
__device__ float  d_gn[NB * NHW * NC];     // unit vectors, [b][n][c]
__device__ float  d_rn[NB * NHW * NC];
__device__ float4 d_part[NB * NCH * NHW * JS];  // per-(i,seg) partial (s, a0, a1, a2)

// packed f32x2 helpers
__device__ __forceinline__ void fma2(unsigned long long& d, unsigned long long a, unsigned long long b) {
    asm("fma.rn.f32x2 %0, %1, %2, %0;" : "+l"(d) : "l"(a), "l"(b));
}
__device__ __forceinline__ float hsum1(unsigned long long a) {
    float lo, hi;
    asm("mov.b64 {%0, %1}, %2;" : "=f"(lo), "=f"(hi) : "l"(a));
    return lo + hi;
}
#define CP_ASYNC16(dst_u32, src_ptr) \
    asm volatile("cp.async.cg.shared.global [%0], [%1], 16;" :: "r"(dst_u32), "l"(src_ptr) : "memory")
#define CP_COMMIT() asm volatile("cp.async.commit_group;" ::: "memory")
#define CP_WAIT0()  asm volatile("cp.async.wait_group 0;" ::: "memory")

// ---------------- kernel 1: classify (per-pixel) + init canvas ----------------
__global__ void __launch_bounds__(256) k_classify(const float* __restrict__ gl,
                                                  const float* __restrict__ rl,
                                                  float* __restrict__ out) {
    int idx = blockIdx.x * 256 + threadIdx.x;          // exact grid: NB*NHW
    out[idx]                = -1.0f;
    out[idx + NB * NHW]     = -1.0f;
    out[idx + 2 * NB * NHW] = -1.0f;

    int b = idx / NHW, n = idx - b * NHW;
    int kg = 0, kr = 0;
#pragma unroll
    for (int k = 0; k < NCH; k++) {
        if (gl[(b * NCH + k) * NHW + n] > 0.5f) kg = k;
        if (rl[(b * NCH + k) * NHW + n] > 0.5f) kr = k;
    }
    d_cls_g[idx] = kg;
    d_cls_r[idx] = kr;
}

// ---------------- kernel 2: fused lists + masked sums ----------------
__global__ void __launch_bounds__(512) k_prep(const float* __restrict__ gf, const float* __restrict__ rf) {
    int tid = threadIdx.x, lane = tid & 31, w = tid >> 5;

    if (blockIdx.x < NB * NCH) {
        int bk = blockIdx.x;
        int b = bk / NCH, k = bk - b * NCH;
        __shared__ int s_wsum[16];
        const int* clsg = d_cls_g + b * NHW;
        const int* clsr = d_cls_r + b * NHW;
        int* lg = d_list_g + (b * NCH + k) * NHW;
        int* lr = d_list_r + (b * NCH + k) * NHW;
        int base_g = 0, base_r = 0;
        for (int n0 = 0; n0 < NHW; n0 += 512) {
            int n = n0 + tid;
            int fg = (n < NHW) && (clsg[n] == k);
            unsigned bal = __ballot_sync(0xffffffffu, fg);
            int wp = __popc(bal & ((1u << lane) - 1u));
            if (lane == 0) s_wsum[w] = __popc(bal);
            __syncthreads();
            int woff = 0, tot = 0;
#pragma unroll
            for (int i = 0; i < 16; i++) { int v = s_wsum[i]; if (i < w) woff += v; tot += v; }
            if (fg) lg[base_g + woff + wp] = n;
            base_g += tot;
            __syncthreads();
            int fr = (n < NHW) && (clsr[n] == k);
            bal = __ballot_sync(0xffffffffu, fr);
            wp = __popc(bal & ((1u << lane) - 1u));
            if (lane == 0) s_wsum[w] = __popc(bal);
            __syncthreads();
            woff = 0; tot = 0;
#pragma unroll
            for (int i = 0; i < 16; i++) { int v = s_wsum[i]; if (i < w) woff += v; tot += v; }
            if (fr) lr[base_r + woff + wp] = n;
            base_r += tot;
            __syncthreads();
        }
        if (tid == 0) { d_cnt_g[b * NCH + k] = base_g; d_cnt_r[b * NCH + k] = base_r; }
    } else {
        int bc = blockIdx.x - NB * NCH;
        int b = bc >> 8, c = bc & 255;
        const float4* g4 = (const float4*)(gf + (b * NC + c) * NHW);
        const float4* r4 = (const float4*)(rf + (b * NC + c) * NHW);
        const int4* cg4 = (const int4*)(d_cls_g + b * NHW);
        const int4* cr4 = (const int4*)(d_cls_r + b * NHW);
        float sg[NCH], sr[NCH];
#pragma unroll
        for (int k = 0; k < NCH; k++) { sg[k] = 0.f; sr[k] = 0.f; }
        for (int q = tid; q < NHW / 4; q += 512) {
            float4 vg = g4[q], vr = r4[q];
            int4 kg = cg4[q], kr = cr4[q];
#pragma unroll
            for (int k = 0; k < NCH; k++) {
                sg[k] += (kg.x == k) ? vg.x : 0.f;
                sg[k] += (kg.y == k) ? vg.y : 0.f;
                sg[k] += (kg.z == k) ? vg.z : 0.f;
                sg[k] += (kg.w == k) ? vg.w : 0.f;
                sr[k] += (kr.x == k) ? vr.x : 0.f;
                sr[k] += (kr.y == k) ? vr.y : 0.f;
                sr[k] += (kr.z == k) ? vr.z : 0.f;
                sr[k] += (kr.w == k) ? vr.w : 0.f;
            }
        }
#pragma unroll
        for (int k = 0; k < NCH; k++) {
#pragma unroll
            for (int off = 16; off; off >>= 1) {
                sg[k] += __shfl_xor_sync(0xffffffffu, sg[k], off);
                sr[k] += __shfl_xor_sync(0xffffffffu, sr[k], off);
            }
        }
        __shared__ float sm[16][2 * NCH];
        if (lane == 0) {
#pragma unroll
            for (int k = 0; k < NCH; k++) { sm[w][k] = sg[k]; sm[w][NCH + k] = sr[k]; }
        }
        __syncthreads();
        if (tid < 2 * NCH) {
            float t = 0.f;
#pragma unroll
            for (int i = 0; i < 16; i++) t += sm[i][tid];
            int k = tid % NCH;
            if (tid >= NCH) d_sum_r[(b * NCH + k) * NC + c] = t;
            else            d_sum_g[(b * NCH + k) * NC + c] = t;
        }
    }
}

// ---------------- kernel 3: normalize + transpose ----------------
__global__ void __launch_bounds__(256) k_normalize(const float* __restrict__ gf, const float* __restrict__ rf) {
    __shared__ float tile[NC][33];
    int b = blockIdx.y;
    int p = blockIdx.z;
    int n0 = blockIdx.x * 32;
    int tid = threadIdx.x, lane = tid & 31, w = tid >> 5;
    const float* f    = (p == 0 ? gf : rf) + b * NC * NHW;
    const int*  cls   = (p == 0 ? d_cls_g : d_cls_r) + b * NHW;
    const float* sums = (p == 0 ? d_sum_g : d_sum_r) + b * NCH * NC;
    const int*  cnts  = (p == 0 ? d_cnt_g : d_cnt_r) + b * NCH;
    float* outp       = (p == 0 ? d_gn : d_rn) + b * NHW * NC;
#pragma unroll
    for (int it = 0; it < 8; it++) {
        int idx = tid + it * 256;
        int c = idx >> 3, q = idx & 7;
        float4 v = ((const float4*)(f + c * NHW + n0))[q];
        tile[c][q * 4 + 0] = v.x;
        tile[c][q * 4 + 1] = v.y;
        tile[c][q * 4 + 2] = v.z;
        tile[c][q * 4 + 3] = v.w;
    }
    __syncthreads();
#pragma unroll
    for (int q = 0; q < 4; q++) {
        int nn = w * 4 + q;
        int n = n0 + nn;
        int k = cls[n];
        float invc = 1.0f / fmaxf((float)cnts[k], 1.0f);
        const float* mk = sums + k * NC;
        float bar[8]; float ss = 0.f;
#pragma unroll
        for (int t = 0; t < 8; t++) {
            int c = lane + 32 * t;
            float v = tile[c][nn] - mk[c] * invc;
            bar[t] = v;
            ss += v * v;
        }
#pragma unroll
        for (int off = 16; off; off >>= 1) ss += __shfl_xor_sync(0xffffffffu, ss, off);
        float norm = sqrtf(ss);
        float inv = (norm > 0.f) ? (1.f / norm) : 1.f;
#pragma unroll
        for (int t = 0; t < 8; t++)
            outp[n * NC + lane + 32 * t] = bar[t] * inv;
    }
}

// ---------------- kernel 4: attention partials (2D lane tile 2i x 4j, 6 wf/c4) ----------------
__global__ void __launch_bounds__(128, 3) k_attn(const float* __restrict__ img) {
    extern __shared__ __align__(16) float smem_dyn[];
    float* rn_s  = smem_dyn;                      // 2 * CBUF
    float* gn_s  = rn_s + 2 * CBUF;               // TI * GSTR
    float* img_s = gn_s + TI * GSTR;              // 2 * TJC * 4 (double-buffered by t&1)
    int*   s_pix = (int*)(img_s + 2 * TJC * 4);   // TI

    int yy = blockIdx.y;
    int k   = (yy % (NCH - 1)) + 1;
    int seg = yy / (NCH - 1);
    int b = blockIdx.z;
    int cg = d_cnt_g[b * NCH + k], cr = d_cnt_r[b * NCH + k];
    if (cg < 2 || cr < 2) return;

    int tid = threadIdx.x, lane = tid & 31, w = tid >> 5;   // w: 0..3
    int u = lane >> 3, v = lane & 7;                        // 2D lane tile
    const int* lg = d_list_g + (b * NCH + k) * NHW;
    const int* lr = d_list_r + (b * NCH + k) * NHW;
    const float4* gn4 = (const float4*)(d_gn + (size_t)b * NHW * NC);
    const float4* rn4 = (const float4*)(d_rn + (size_t)b * NHW * NC);
    const float* imgb = img + b * 3 * NHW;
    float4* partp = d_part + (size_t)(b * NCH + k) * NHW * JS;

    uint32_t rn_su = (uint32_t)__cvta_generic_to_shared(rn_s);
    // rn fill: 1024 float4 per sub-tile (32 rows x 32 f4), 8 per thread
    int f_row  = tid >> 5;      // 0..3; rows f_row + 4*it
    int f_col4 = tid & 31;      // 0..31

    int nT   = (cr + TJC - 1) / TJC;
    int tBeg = (seg * nT) / JS, tEnd = ((seg + 1) * nT) / JS;
    int sBeg = 2 * tBeg, nSub = 2 * (tEnd - tBeg);   // nSub EVEN

    int I0 = w * 8 + u * 2;     // local i of this lane's first row

    for (int i_base = blockIdx.x * TI; i_base < cg; i_base += GX * TI) {
        __syncthreads();
        if (tid < TI) s_pix[tid] = lg[min(i_base + tid, cg - 1)];

        // prologue: rn prefetch of first sub-tile (h=0) into buffer 0 + img tile for tBeg
        if (nSub > 0) {
            int j0 = tBeg * TJC;
#pragma unroll
            for (int it = 0; it < 8; it++) {
                int row = f_row + 4 * it;
                int jp = __ldg(lr + min(j0 + row, cr - 1));
                uint32_t dst = rn_su + (uint32_t)((row * CSTR + f_col4 * 4) * 4);
                CP_ASYNC16(dst, rn4 + (size_t)jp * 64 + f_col4);
            }
            CP_COMMIT();
            if (tid < TJC) {
                int jp = __ldg(lr + min(j0 + tid, cr - 1));
                float* ib = img_s + (tBeg & 1) * TJC * 4 + tid * 4;
                ib[0] = __ldg(imgb + 0 * NHW + jp);
                ib[1] = __ldg(imgb + 1 * NHW + jp);
                ib[2] = __ldg(imgb + 2 * NHW + jp);
            }
        }
        __syncthreads();    // s_pix visible for gn fill

        // gn tile: TI rows x 64 f4, padded row stride 65 f4
#pragma unroll
        for (int it = 0; it < (TI * 64) / 128; it++) {
            int idx = tid + it * 128;
            int row = idx >> 6, col4 = idx & 63;
            ((float4*)gn_s)[row * 65 + col4] = gn4[s_pix[row] * 64 + col4];
        }

        // per-lane partial softmax state for 2 i's
        float sp[2] = {0.f, 0.f}, p0[2] = {0.f, 0.f}, p1[2] = {0.f, 0.f}, p2[2] = {0.f, 0.f};
        unsigned long long acc[2][4];

        for (int q = 0; q < nSub; q++) {
            int s = sBeg + q;
            int t = s >> 1, h = s & 1;
            int buf = q & 1;

            CP_WAIT0();
            __syncthreads();     // tile q visible; buffer (1-buf) free; img tiles settled

            // prefetch tile q+1 (rn always; img only when it starts a new j-tile)
            if (q + 1 < nSub) {
                int s2 = s + 1;
                int t2 = s2 >> 1, h2 = s2 & 1;
                int j0n = t2 * TJC;
                uint32_t base = rn_su + (uint32_t)((1 - buf) * CBUF * 4);
#pragma unroll
                for (int it = 0; it < 8; it++) {
                    int row = f_row + 4 * it;
                    int jp = __ldg(lr + min(j0n + row, cr - 1));
                    uint32_t dst = base + (uint32_t)((row * CSTR + f_col4 * 4) * 4);
                    CP_ASYNC16(dst, rn4 + (size_t)jp * 64 + h2 * 32 + f_col4);
                }
                CP_COMMIT();
                if (h2 == 0 && tid < TJC) {      // new j-tile t2: stage its img into buffer t2&1
                    int jp = __ldg(lr + min(j0n + tid, cr - 1));
                    float* ib = img_s + (t2 & 1) * TJC * 4 + tid * 4;
                    ib[0] = __ldg(imgb + 0 * NHW + jp);
                    ib[1] = __ldg(imgb + 1 * NHW + jp);
                    ib[2] = __ldg(imgb + 2 * NHW + jp);
                }
            }

            if (h == 0) {
#pragma unroll
                for (int e = 0; e < 2; e++)
#pragma unroll
                    for (int jj = 0; jj < 4; jj++) acc[e][jj] = 0;
            }

            // dot: 2i x 4j register tile; 6 LDS wavefronts per c4
            const ulonglong2* gp0 = (const ulonglong2*)(gn_s + (size_t)I0 * GSTR + h * CH);
            const ulonglong2* gp1 = (const ulonglong2*)(gn_s + (size_t)(I0 + 1) * GSTR + h * CH);
            const ulonglong2* rp0 = (const ulonglong2*)(rn_s + buf * CBUF + (v + 0) * CSTR);
            const ulonglong2* rp1 = (const ulonglong2*)(rn_s + buf * CBUF + (v + 8) * CSTR);
            const ulonglong2* rp2 = (const ulonglong2*)(rn_s + buf * CBUF + (v + 16) * CSTR);
            const ulonglong2* rp3 = (const ulonglong2*)(rn_s + buf * CBUF + (v + 24) * CSTR);
#pragma unroll
            for (int c4 = 0; c4 < CH / 4; c4++) {
                ulonglong2 g0 = gp0[c4], g1 = gp1[c4];
                ulonglong2 r0 = rp0[c4], r1 = rp1[c4], r2 = rp2[c4], r3 = rp3[c4];
                fma2(acc[0][0], r0.x, g0.x); fma2(acc[0][0], r0.y, g0.y);
                fma2(acc[0][1], r1.x, g0.x); fma2(acc[0][1], r1.y, g0.y);
                fma2(acc[0][2], r2.x, g0.x); fma2(acc[0][2], r2.y, g0.y);
                fma2(acc[0][3], r3.x, g0.x); fma2(acc[0][3], r3.y, g0.y);
                fma2(acc[1][0], r0.x, g1.x); fma2(acc[1][0], r0.y, g1.y);
                fma2(acc[1][1], r1.x, g1.x); fma2(acc[1][1], r1.y, g1.y);
                fma2(acc[1][2], r2.x, g1.x); fma2(acc[1][2], r2.y, g1.y);
                fma2(acc[1][3], r3.x, g1.x); fma2(acc[1][3], r3.y, g1.y);
            }

            if (h == 1) {
                int j0 = t * TJC;
                const float* ib = img_s + (t & 1) * TJC * 4;
#pragma unroll
                for (int jj = 0; jj < 4; jj++) {
                    int J = v + 8 * jj;
                    bool val = (j0 + J) < cr;
                    float i0v = ib[J * 4 + 0];
                    float i1v = ib[J * 4 + 1];
                    float i2v = ib[J * 4 + 2];
#pragma unroll
                    for (int e = 0; e < 2; e++) {
                        float d = hsum1(acc[e][jj]);
                        float ex = val ? __expf(d) : 0.f;   // logits in [-1,1]: no max tracking
                        sp[e] += ex;
                        p0[e] += ex * i0v;
                        p1[e] += ex * i1v;
                        p2[e] += ex * i2v;
                    }
                }
            }
        }

        // octet reduce (over v), write partials
#pragma unroll
        for (int e = 0; e < 2; e++) {
            float s_ = sp[e], x = p0[e], y = p1[e], z = p2[e];
#pragma unroll
            for (int off = 1; off <= 4; off <<= 1) {
                s_ += __shfl_xor_sync(0xffffffffu, s_, off);
                x  += __shfl_xor_sync(0xffffffffu, x, off);
                y  += __shfl_xor_sync(0xffffffffu, y, off);
                z  += __shfl_xor_sync(0xffffffffu, z, off);
            }
            int ig = i_base + I0 + e;
            if (v == 0 && ig < cg) {
                partp[ig * JS + seg] = make_float4(s_, x, y, z);
            }
        }
    }
}

// ---------------- kernel 5: merge partials, divide, scatter ----------------
__global__ void __launch_bounds__(256) k_merge(float* __restrict__ out) {
    int bk = blockIdx.x;                       // 0..21
    int b = bk / (NCH - 1), k = bk % (NCH - 1) + 1;
    int cg = d_cnt_g[b * NCH + k], cr = d_cnt_r[b * NCH + k];
    if (cg < 2 || cr < 2) return;
    const int* lg = d_list_g + (b * NCH + k) * NHW;
    const float4* partp = d_part + (size_t)(b * NCH + k) * NHW * JS;
    for (int i = threadIdx.x; i < cg; i += 256) {
        float s = 0.f, x = 0.f, y = 0.f, z = 0.f;
#pragma unroll
        for (int p = 0; p < JS; p++) {
            float4 P = partp[i * JS + p];
            s += P.x; x += P.y; y += P.z; z += P.w;
        }
        float inv = 1.0f / s;
        int pix = lg[i];
        out[b * 3 * NHW + 0 * NHW + pix] = x * inv;
        out[b * 3 * NHW + 1 * NHW + pix] = y * inv;
        out[b * 3 * NHW + 2 * NHW + pix] = z * inv;
    }
}

// ---------------- launch ----------------
extern "C" void kernel_launch(void* const* d_in, const int* in_sizes, int n_in,
                              void* d_out, int out_size) {
    (void)in_sizes; (void)n_in; (void)out_size;
    const float* gf  = (const float*)d_in[0];
    const float* rf  = (const float*)d_in[1];
    const float* img = (const float*)d_in[2];
    const float* gl  = (const float*)d_in[3];
    const float* rl  = (const float*)d_in[4];
    float* out = (float*)d_out;

    cudaFuncSetAttribute(k_attn, cudaFuncAttributeMaxDynamicSharedMemorySize, ATTN_SMEM);

    k_classify<<<NB * NHW / 256, 256>>>(gl, rl, out);
    k_prep<<<NB * NCH + NB * NC, 512>>>(gf, rf);
    k_normalize<<<dim3(NHW / 32, NB, 2), 256>>>(gf, rf);
    k_attn<<<dim3(GX, (NCH - 1) * JS, NB), 128, ATTN_SMEM>>>(img);
    k_merge<<<NB * (NCH - 1), 256>>>(out);
}

// round 15
// speedup vs baseline: 1.0491x; 1.0491x over previous
#include <cuda_runtime.h>
#include <math.h>
#include <stdint.h>

#define NB   2
#define NC   256
#define NHW  2304     // 48*48
#define NCH  12

#define TI   32       // gray pixels per attention block (4 warps x 8 i)
#define TJC  32       // rgb pixels per smem tile
#define CH   128      // channel half per sub-tile (long phases: 32 c4-iters)
#define CSTR 132      // rn row stride (floats): conflict-free
#define GSTR 260      // gn row stride (floats): conflict-free g-frag (65 f4)
#define CBUF (TJC*CSTR)           // floats per rn buffer (4224 = 16.9KB)
#define GX   7        // attention grid.x
#define JS   3        // j segments -> grid 462 blocks ~ 3.1/SM

#define ATTN_SMEM ((2*CBUF + TI*GSTR + 2*TJC*4)*4 + TI*4 + 32)

// ---------------- scratch ----------------
__device__ int    d_cls_g[NB * NHW];
__device__ int    d_cls_r[NB * NHW];
__device__ int    d_list_g[NB * NCH * NHW];
__device__ int    d_list_r[NB * NCH * NHW];
__device__ int    d_cnt_g[NB * NCH];
__device__ int    d_cnt_r[NB * NCH];
__device__ float  d_sum_g[NB * NCH * NC];
__device__ float  d_sum_r[NB * NCH * NC];
__device__ float  d_gn[NB * NHW * NC];     // unit vectors, [b][n][c]
__device__ float  d_rn[NB * NHW * NC];
__device__ float4 d_part[NB * NCH * NHW * JS];  // per-(i,seg) partial (s, a0, a1, a2)
__device__ int    d_ticket[NB * NCH];           // completion counters for fused merge

// packed f32x2 helpers
__device__ __forceinline__ void fma2(unsigned long long& d, unsigned long long a, unsigned long long b) {
    asm("fma.rn.f32x2 %0, %1, %2, %0;" : "+l"(d) : "l"(a), "l"(b));
}
__device__ __forceinline__ float hsum1(unsigned long long a) {
    float lo, hi;
    asm("mov.b64 {%0, %1}, %2;" : "=f"(lo), "=f"(hi) : "l"(a));
    return lo + hi;
}
#define CP_ASYNC16(dst_u32, src_ptr) \
    asm volatile("cp.async.cg.shared.global [%0], [%1], 16;" :: "r"(dst_u32), "l"(src_ptr) : "memory")
#define CP_COMMIT() asm volatile("cp.async.commit_group;" ::: "memory")
#define CP_WAIT0()  asm volatile("cp.async.wait_group 0;" ::: "memory")

// ---------------- kernel 1: classify (per-pixel) + init canvas + reset tickets ----------------
__global__ void __launch_bounds__(256) k_classify(const float* __restrict__ gl,
                                                  const float* __restrict__ rl,
                                                  float* __restrict__ out) {
    int idx = blockIdx.x * 256 + threadIdx.x;          // exact grid: NB*NHW
    out[idx]                = -1.0f;
    out[idx + NB * NHW]     = -1.0f;
    out[idx + 2 * NB * NHW] = -1.0f;
    if (idx < NB * NCH) d_ticket[idx] = 0;

    int b = idx / NHW, n = idx - b * NHW;
    int kg = 0, kr = 0;
#pragma unroll
    for (int k = 0; k < NCH; k++) {
        if (gl[(b * NCH + k) * NHW + n] > 0.5f) kg = k;
        if (rl[(b * NCH + k) * NHW + n] > 0.5f) kr = k;
    }
    d_cls_g[idx] = kg;
    d_cls_r[idx] = kr;
}

// ---------------- kernel 2: fused lists + masked sums ----------------
__global__ void __launch_bounds__(512) k_prep(const float* __restrict__ gf, const float* __restrict__ rf) {
    int tid = threadIdx.x, lane = tid & 31, w = tid >> 5;

    if (blockIdx.x < NB * NCH) {
        int bk = blockIdx.x;
        int b = bk / NCH, k = bk - b * NCH;
        __shared__ int s_wsum[16];
        const int* clsg = d_cls_g + b * NHW;
        const int* clsr = d_cls_r + b * NHW;
        int* lg = d_list_g + (b * NCH + k) * NHW;
        int* lr = d_list_r + (b * NCH + k) * NHW;
        int base_g = 0, base_r = 0;
        for (int n0 = 0; n0 < NHW; n0 += 512) {
            int n = n0 + tid;
            int fg = (n < NHW) && (clsg[n] == k);
            unsigned bal = __ballot_sync(0xffffffffu, fg);
            int wp = __popc(bal & ((1u << lane) - 1u));
            if (lane == 0) s_wsum[w] = __popc(bal);
            __syncthreads();
            int woff = 0, tot = 0;
#pragma unroll
            for (int i = 0; i < 16; i++) { int v = s_wsum[i]; if (i < w) woff += v; tot += v; }
            if (fg) lg[base_g + woff + wp] = n;
            base_g += tot;
            __syncthreads();
            int fr = (n < NHW) && (clsr[n] == k);
            bal = __ballot_sync(0xffffffffu, fr);
            wp = __popc(bal & ((1u << lane) - 1u));
            if (lane == 0) s_wsum[w] = __popc(bal);
            __syncthreads();
            woff = 0; tot = 0;
#pragma unroll
            for (int i = 0; i < 16; i++) { int v = s_wsum[i]; if (i < w) woff += v; tot += v; }
            if (fr) lr[base_r + woff + wp] = n;
            base_r += tot;
            __syncthreads();
        }
        if (tid == 0) { d_cnt_g[b * NCH + k] = base_g; d_cnt_r[b * NCH + k] = base_r; }
    } else {
        int bc = blockIdx.x - NB * NCH;
        int b = bc >> 8, c = bc & 255;
        const float4* g4 = (const float4*)(gf + (b * NC + c) * NHW);
        const float4* r4 = (const float4*)(rf + (b * NC + c) * NHW);
        const int4* cg4 = (const int4*)(d_cls_g + b * NHW);
        const int4* cr4 = (const int4*)(d_cls_r + b * NHW);
        float sg[NCH], sr[NCH];
#pragma unroll
        for (int k = 0; k < NCH; k++) { sg[k] = 0.f; sr[k] = 0.f; }
        for (int q = tid; q < NHW / 4; q += 512) {
            float4 vg = g4[q], vr = r4[q];
            int4 kg = cg4[q], kr = cr4[q];
#pragma unroll
            for (int k = 0; k < NCH; k++) {
                sg[k] += (kg.x == k) ? vg.x : 0.f;
                sg[k] += (kg.y == k) ? vg.y : 0.f;
                sg[k] += (kg.z == k) ? vg.z : 0.f;
                sg[k] += (kg.w == k) ? vg.w : 0.f;
                sr[k] += (kr.x == k) ? vr.x : 0.f;
                sr[k] += (kr.y == k) ? vr.y : 0.f;
                sr[k] += (kr.z == k) ? vr.z : 0.f;
                sr[k] += (kr.w == k) ? vr.w : 0.f;
            }
        }
#pragma unroll
        for (int k = 0; k < NCH; k++) {
#pragma unroll
            for (int off = 16; off; off >>= 1) {
                sg[k] += __shfl_xor_sync(0xffffffffu, sg[k], off);
                sr[k] += __shfl_xor_sync(0xffffffffu, sr[k], off);
            }
        }
        __shared__ float sm[16][2 * NCH];
        if (lane == 0) {
#pragma unroll
            for (int k = 0; k < NCH; k++) { sm[w][k] = sg[k]; sm[w][NCH + k] = sr[k]; }
        }
        __syncthreads();
        if (tid < 2 * NCH) {
            float t = 0.f;
#pragma unroll
            for (int i = 0; i < 16; i++) t += sm[i][tid];
            int k = tid % NCH;
            if (tid >= NCH) d_sum_r[(b * NCH + k) * NC + c] = t;
            else            d_sum_g[(b * NCH + k) * NC + c] = t;
        }
    }
}

// ---------------- kernel 3: normalize + transpose ----------------
__global__ void __launch_bounds__(256) k_normalize(const float* __restrict__ gf, const float* __restrict__ rf) {
    __shared__ float tile[NC][33];
    int b = blockIdx.y;
    int p = blockIdx.z;
    int n0 = blockIdx.x * 32;
    int tid = threadIdx.x, lane = tid & 31, w = tid >> 5;
    const float* f    = (p == 0 ? gf : rf) + b * NC * NHW;
    const int*  cls   = (p == 0 ? d_cls_g : d_cls_r) + b * NHW;
    const float* sums = (p == 0 ? d_sum_g : d_sum_r) + b * NCH * NC;
    const int*  cnts  = (p == 0 ? d_cnt_g : d_cnt_r) + b * NCH;
    float* outp       = (p == 0 ? d_gn : d_rn) + b * NHW * NC;
#pragma unroll
    for (int it = 0; it < 8; it++) {
        int idx = tid + it * 256;
        int c = idx >> 3, q = idx & 7;
        float4 v = ((const float4*)(f + c * NHW + n0))[q];
        tile[c][q * 4 + 0] = v.x;
        tile[c][q * 4 + 1] = v.y;
        tile[c][q * 4 + 2] = v.z;
        tile[c][q * 4 + 3] = v.w;
    }
    __syncthreads();
#pragma unroll
    for (int q = 0; q < 4; q++) {
        int nn = w * 4 + q;
        int n = n0 + nn;
        int k = cls[n];
        float invc = 1.0f / fmaxf((float)cnts[k], 1.0f);
        const float* mk = sums + k * NC;
        float bar[8]; float ss = 0.f;
#pragma unroll
        for (int t = 0; t < 8; t++) {
            int c = lane + 32 * t;
            float v = tile[c][nn] - mk[c] * invc;
            bar[t] = v;
            ss += v * v;
        }
#pragma unroll
        for (int off = 16; off; off >>= 1) ss += __shfl_xor_sync(0xffffffffu, ss, off);
        float norm = sqrtf(ss);
        float inv = (norm > 0.f) ? (1.f / norm) : 1.f;
#pragma unroll
        for (int t = 0; t < 8; t++)
            outp[n * NC + lane + 32 * t] = bar[t] * inv;
    }
}

// ---------------- kernel 4: attention + fused merge (atomic ticket) ----------------
__global__ void __launch_bounds__(128, 3) k_attn(const float* __restrict__ img, float* __restrict__ out) {
    extern __shared__ __align__(16) float smem_dyn[];
    float* rn_s  = smem_dyn;                      // 2 * CBUF
    float* gn_s  = rn_s + 2 * CBUF;               // TI * GSTR
    float* img_s = gn_s + TI * GSTR;              // 2 * TJC * 4
    int*   s_pix = (int*)(img_s + 2 * TJC * 4);   // TI
    int*   s_last = s_pix + TI;                   // 1

    int yy = blockIdx.y;
    int k   = (yy % (NCH - 1)) + 1;
    int seg = yy / (NCH - 1);
    int b = blockIdx.z;
    int bk = b * NCH + k;
    int cg = d_cnt_g[bk], cr = d_cnt_r[bk];
    if (cg < 2 || cr < 2) return;

    int tid = threadIdx.x, lane = tid & 31, w = tid >> 5;   // w: 0..3
    int u = lane >> 3, v = lane & 7;                        // 2D lane tile
    const int* lg = d_list_g + bk * NHW;
    const int* lr = d_list_r + bk * NHW;
    const float4* gn4 = (const float4*)(d_gn + (size_t)b * NHW * NC);
    const float4* rn4 = (const float4*)(d_rn + (size_t)b * NHW * NC);
    const float* imgb = img + b * 3 * NHW;
    float4* partp = d_part + (size_t)bk * NHW * JS;

    uint32_t rn_su = (uint32_t)__cvta_generic_to_shared(rn_s);
    uint32_t gn_su = (uint32_t)__cvta_generic_to_shared(gn_s);
    int f_row  = tid >> 5;      // 0..3; rn fill rows f_row + 4*it
    int f_col4 = tid & 31;      // 0..31

    int nT   = (cr + TJC - 1) / TJC;
    int tBeg = (seg * nT) / JS, tEnd = ((seg + 1) * nT) / JS;
    int sBeg = 2 * tBeg, nSub = 2 * (tEnd - tBeg);   // nSub EVEN

    int I0 = w * 8 + u * 2;     // local i of this lane's first row

    for (int i_base = blockIdx.x * TI; i_base < cg; i_base += GX * TI) {
        __syncthreads();
        if (tid < TI) s_pix[tid] = lg[min(i_base + tid, cg - 1)];
        __syncthreads();    // s_pix visible

        // prologue: cp.async gn tile + rn sub-tile 0 + img tile, one commit group
        if (nSub > 0) {
            // gn tile: 2048 f4, 16 per thread, padded row stride 65 f4
#pragma unroll
            for (int it = 0; it < (TI * 64) / 128; it++) {
                int idx = tid + it * 128;
                int row = idx >> 6, col4 = idx & 63;
                uint32_t dst = gn_su + (uint32_t)((row * 65 + col4) * 16);
                CP_ASYNC16(dst, gn4 + (size_t)s_pix[row] * 64 + col4);
            }
            int j0 = tBeg * TJC;
#pragma unroll
            for (int it = 0; it < 8; it++) {
                int row = f_row + 4 * it;
                int jp = __ldg(lr + min(j0 + row, cr - 1));
                uint32_t dst = rn_su + (uint32_t)((row * CSTR + f_col4 * 4) * 4);
                CP_ASYNC16(dst, rn4 + (size_t)jp * 64 + f_col4);
            }
            CP_COMMIT();
            if (tid < TJC) {
                int jp = __ldg(lr + min(j0 + tid, cr - 1));
                float* ib = img_s + (tBeg & 1) * TJC * 4 + tid * 4;
                ib[0] = __ldg(imgb + 0 * NHW + jp);
                ib[1] = __ldg(imgb + 1 * NHW + jp);
                ib[2] = __ldg(imgb + 2 * NHW + jp);
            }
        }

        float sp[2] = {0.f, 0.f}, p0[2] = {0.f, 0.f}, p1[2] = {0.f, 0.f}, p2[2] = {0.f, 0.f};
        unsigned long long acc[2][4];

        for (int q = 0; q < nSub; q++) {
            int s = sBeg + q;
            int t = s >> 1, h = s & 1;
            int buf = q & 1;

            CP_WAIT0();
            __syncthreads();     // tile q (and gn at q=0) visible; buffer (1-buf) free

            if (q + 1 < nSub) {
                int s2 = s + 1;
                int t2 = s2 >> 1, h2 = s2 & 1;
                int j0n = t2 * TJC;
                uint32_t base = rn_su + (uint32_t)((1 - buf) * CBUF * 4);
#pragma unroll
                for (int it = 0; it < 8; it++) {
                    int row = f_row + 4 * it;
                    int jp = __ldg(lr + min(j0n + row, cr - 1));
                    uint32_t dst = base + (uint32_t)((row * CSTR + f_col4 * 4) * 4);
                    CP_ASYNC16(dst, rn4 + (size_t)jp * 64 + h2 * 32 + f_col4);
                }
                CP_COMMIT();
                if (h2 == 0 && tid < TJC) {
                    int jp = __ldg(lr + min(j0n + tid, cr - 1));
                    float* ib = img_s + (t2 & 1) * TJC * 4 + tid * 4;
                    ib[0] = __ldg(imgb + 0 * NHW + jp);
                    ib[1] = __ldg(imgb + 1 * NHW + jp);
                    ib[2] = __ldg(imgb + 2 * NHW + jp);
                }
            }

            if (h == 0) {
#pragma unroll
                for (int e = 0; e < 2; e++)
#pragma unroll
                    for (int jj = 0; jj < 4; jj++) acc[e][jj] = 0;
            }

            const ulonglong2* gp0 = (const ulonglong2*)(gn_s + (size_t)I0 * GSTR + h * CH);
            const ulonglong2* gp1 = (const ulonglong2*)(gn_s + (size_t)(I0 + 1) * GSTR + h * CH);
            const ulonglong2* rp0 = (const ulonglong2*)(rn_s + buf * CBUF + (v + 0) * CSTR);
            const ulonglong2* rp1 = (const ulonglong2*)(rn_s + buf * CBUF + (v + 8) * CSTR);
            const ulonglong2* rp2 = (const ulonglong2*)(rn_s + buf * CBUF + (v + 16) * CSTR);
            const ulonglong2* rp3 = (const ulonglong2*)(rn_s + buf * CBUF + (v + 24) * CSTR);
#pragma unroll
            for (int c4 = 0; c4 < CH / 4; c4++) {
                ulonglong2 g0 = gp0[c4], g1 = gp1[c4];
                ulonglong2 r0 = rp0[c4], r1 = rp1[c4], r2 = rp2[c4], r3 = rp3[c4];
                fma2(acc[0][0], r0.x, g0.x); fma2(acc[0][0], r0.y, g0.y);
                fma2(acc[0][1], r1.x, g0.x); fma2(acc[0][1], r1.y, g0.y);
                fma2(acc[0][2], r2.x, g0.x); fma2(acc[0][2], r2.y, g0.y);
                fma2(acc[0][3], r3.x, g0.x); fma2(acc[0][3], r3.y, g0.y);
                fma2(acc[1][0], r0.x, g1.x); fma2(acc[1][0], r0.y, g1.y);
                fma2(acc[1][1], r1.x, g1.x); fma2(acc[1][1], r1.y, g1.y);
                fma2(acc[1][2], r2.x, g1.x); fma2(acc[1][2], r2.y, g1.y);
                fma2(acc[1][3], r3.x, g1.x); fma2(acc[1][3], r3.y, g1.y);
            }

            if (h == 1) {
                int j0 = t * TJC;
                const float* ib = img_s + (t & 1) * TJC * 4;
#pragma unroll
                for (int jj = 0; jj < 4; jj++) {
                    int J = v + 8 * jj;
                    bool val = (j0 + J) < cr;
                    float i0v = ib[J * 4 + 0];
                    float i1v = ib[J * 4 + 1];
                    float i2v = ib[J * 4 + 2];
#pragma unroll
                    for (int e = 0; e < 2; e++) {
                        float d = hsum1(acc[e][jj]);
                        float ex = val ? __expf(d) : 0.f;   // logits in [-1,1]: no max tracking
                        sp[e] += ex;
                        p0[e] += ex * i0v;
                        p1[e] += ex * i1v;
                        p2[e] += ex * i2v;
                    }
                }
            }
        }

        // octet reduce (over v), write partials
#pragma unroll
        for (int e = 0; e < 2; e++) {
            float s_ = sp[e], x = p0[e], y = p1[e], z = p2[e];
#pragma unroll
            for (int off = 1; off <= 4; off <<= 1) {
                s_ += __shfl_xor_sync(0xffffffffu, s_, off);
                x  += __shfl_xor_sync(0xffffffffu, x, off);
                y  += __shfl_xor_sync(0xffffffffu, y, off);
                z  += __shfl_xor_sync(0xffffffffu, z, off);
            }
            int ig = i_base + I0 + e;
            if (v == 0 && ig < cg) {
                partp[ig * JS + seg] = make_float4(s_, x, y, z);
            }
        }
    }

    // ---- fused merge: last of GX*JS blocks for this (b,k) sums partials + scatters ----
    __threadfence();
    __syncthreads();
    if (tid == 0) {
        int old = atomicAdd(&d_ticket[bk], 1);
        *s_last = (old == GX * JS - 1) ? 1 : 0;
    }
    __syncthreads();
    if (*s_last) {
        __threadfence();
        for (int i = tid; i < cg; i += 128) {
            float s = 0.f, x = 0.f, y = 0.f, z = 0.f;
#pragma unroll
            for (int p = 0; p < JS; p++) {
                float4 P = partp[i * JS + p];
                s += P.x; x += P.y; y += P.z; z += P.w;
            }
            float inv = 1.0f / s;
            int pix = lg[i];
            out[b * 3 * NHW + 0 * NHW + pix] = x * inv;
            out[b * 3 * NHW + 1 * NHW + pix] = y * inv;
            out[b * 3 * NHW + 2 * NHW + pix] = z * inv;
        }
    }
}

// ---------------- launch ----------------
extern "C" void kernel_launch(void* const* d_in, const int* in_sizes, int n_in,
                              void* d_out, int out_size) {
    (void)in_sizes; (void)n_in; (void)out_size;
    const float* gf  = (const float*)d_in[0];
    const float* rf  = (const float*)d_in[1];
    const float* img = (const float*)d_in[2];
    const float* gl  = (const float*)d_in[3];
    const float* rl  = (const float*)d_in[4];
    float* out = (float*)d_out;

    cudaFuncSetAttribute(k_attn, cudaFuncAttributeMaxDynamicSharedMemorySize, ATTN_SMEM);

    k_classify<<<NB * NHW / 256, 256>>>(gl, rl, out);
    k_prep<<<NB * NCH + NB * NC, 512>>>(gf, rf);
    k_normalize<<<dim3(NHW / 32, NB, 2), 256>>>(gf, rf);
    k_attn<<<dim3(GX, (NCH - 1) * JS, NB), 128, ATTN_SMEM>>>(img, out);
}

// round 16
// speedup vs baseline: 1.0963x; 1.0450x over previous
#include <cuda_runtime.h>
#include <math.h>
#include <stdint.h>

#define NB   2
#define NC   256
#define NHW  2304     // 48*48
#define NCH  12

#define TI   32       // gray pixels per attention block (4 warps x 8 i)
#define TJC  32       // rgb pixels per smem tile
#define CH   128      // channel half per sub-tile (long phases: 32 c4-iters)
#define CSTR 132      // rn row stride (floats): conflict-free
#define GSTR 260      // gn row stride (floats): conflict-free g-frag (65 f4)
#define CBUF (TJC*CSTR)           // floats per rn buffer (4224 = 16.9KB)
#define GX   7        // attention grid.x
#define JS   3        // j segments -> grid 462 blocks ~ 3.1/SM

#define ATTN_SMEM ((2*CBUF + TI*GSTR + 2*TJC*4)*4 + TI*4 + 32)

// ---------------- scratch ----------------
__device__ int    d_cls_g[NB * NHW];
__device__ int    d_cls_r[NB * NHW];
__device__ int    d_list_g[NB * NCH * NHW];
__device__ int    d_list_r[NB * NCH * NHW];
__device__ int    d_cnt_g[NB * NCH];
__device__ int    d_cnt_r[NB * NCH];
__device__ float  d_sum_g[NB * NCH * NC];
__device__ float  d_sum_r[NB * NCH * NC];
__device__ float  d_gn[NB * NHW * NC];     // unit vectors, [b][n][c]
__device__ float  d_rn[NB * NHW * NC];
__device__ float4 d_part[NB * NCH * NHW * JS];  // per-(i,seg) partial (s, a0, a1, a2)
__device__ int    d_ticket[NB * NCH];           // completion counters for fused merge

// packed f32x2 helpers
__device__ __forceinline__ void fma2(unsigned long long& d, unsigned long long a, unsigned long long b) {
    asm("fma.rn.f32x2 %0, %1, %2, %0;" : "+l"(d) : "l"(a), "l"(b));
}
__device__ __forceinline__ float hsum1(unsigned long long a) {
    float lo, hi;
    asm("mov.b64 {%0, %1}, %2;" : "=f"(lo), "=f"(hi) : "l"(a));
    return lo + hi;
}
#define CP_ASYNC16(dst_u32, src_ptr) \
    asm volatile("cp.async.cg.shared.global [%0], [%1], 16;" :: "r"(dst_u32), "l"(src_ptr) : "memory")
#define CP_COMMIT() asm volatile("cp.async.commit_group;" ::: "memory")
#define CP_WAIT0()  asm volatile("cp.async.wait_group 0;" ::: "memory")

// ---------------- kernel 1: classify (per-pixel) + init canvas + reset tickets ----------------
__global__ void __launch_bounds__(256) k_classify(const float* __restrict__ gl,
                                                  const float* __restrict__ rl,
                                                  float* __restrict__ out) {
    int idx = blockIdx.x * 256 + threadIdx.x;          // exact grid: NB*NHW
    out[idx]                = -1.0f;
    out[idx + NB * NHW]     = -1.0f;
    out[idx + 2 * NB * NHW] = -1.0f;
    if (idx < NB * NCH) d_ticket[idx] = 0;

    int b = idx / NHW, n = idx - b * NHW;
    int kg = 0, kr = 0;
#pragma unroll
    for (int k = 0; k < NCH; k++) {
        if (gl[(b * NCH + k) * NHW + n] > 0.5f) kg = k;
        if (rl[(b * NCH + k) * NHW + n] > 0.5f) kr = k;
    }
    d_cls_g[idx] = kg;
    d_cls_r[idx] = kr;
}

// ---------------- kernel 2: fused lists + masked sums ----------------
__global__ void __launch_bounds__(512) k_prep(const float* __restrict__ gf, const float* __restrict__ rf) {
    int tid = threadIdx.x, lane = tid & 31, w = tid >> 5;

    if (blockIdx.x < NB * NCH) {
        int bk = blockIdx.x;
        int b = bk / NCH, k = bk - b * NCH;
        __shared__ int s_wsum[16];
        const int* clsg = d_cls_g + b * NHW;
        const int* clsr = d_cls_r + b * NHW;
        int* lg = d_list_g + (b * NCH + k) * NHW;
        int* lr = d_list_r + (b * NCH + k) * NHW;
        int base_g = 0, base_r = 0;
        for (int n0 = 0; n0 < NHW; n0 += 512) {
            int n = n0 + tid;
            int fg = (n < NHW) && (clsg[n] == k);
            unsigned bal = __ballot_sync(0xffffffffu, fg);
            int wp = __popc(bal & ((1u << lane) - 1u));
            if (lane == 0) s_wsum[w] = __popc(bal);
            __syncthreads();
            int woff = 0, tot = 0;
#pragma unroll
            for (int i = 0; i < 16; i++) { int v = s_wsum[i]; if (i < w) woff += v; tot += v; }
            if (fg) lg[base_g + woff + wp] = n;
            base_g += tot;
            __syncthreads();
            int fr = (n < NHW) && (clsr[n] == k);
            bal = __ballot_sync(0xffffffffu, fr);
            wp = __popc(bal & ((1u << lane) - 1u));
            if (lane == 0) s_wsum[w] = __popc(bal);
            __syncthreads();
            woff = 0; tot = 0;
#pragma unroll
            for (int i = 0; i < 16; i++) { int v = s_wsum[i]; if (i < w) woff += v; tot += v; }
            if (fr) lr[base_r + woff + wp] = n;
            base_r += tot;
            __syncthreads();
        }
        if (tid == 0) { d_cnt_g[b * NCH + k] = base_g; d_cnt_r[b * NCH + k] = base_r; }
    } else {
        int bc = blockIdx.x - NB * NCH;
        int b = bc >> 8, c = bc & 255;
        const float4* g4 = (const float4*)(gf + (b * NC + c) * NHW);
        const float4* r4 = (const float4*)(rf + (b * NC + c) * NHW);
        const int4* cg4 = (const int4*)(d_cls_g + b * NHW);
        const int4* cr4 = (const int4*)(d_cls_r + b * NHW);
        float sg[NCH], sr[NCH];
#pragma unroll
        for (int k = 0; k < NCH; k++) { sg[k] = 0.f; sr[k] = 0.f; }
        for (int q = tid; q < NHW / 4; q += 512) {
            float4 vg = g4[q], vr = r4[q];
            int4 kg = cg4[q], kr = cr4[q];
#pragma unroll
            for (int k = 0; k < NCH; k++) {
                sg[k] += (kg.x == k) ? vg.x : 0.f;
                sg[k] += (kg.y == k) ? vg.y : 0.f;
                sg[k] += (kg.z == k) ? vg.z : 0.f;
                sg[k] += (kg.w == k) ? vg.w : 0.f;
                sr[k] += (kr.x == k) ? vr.x : 0.f;
                sr[k] += (kr.y == k) ? vr.y : 0.f;
                sr[k] += (kr.z == k) ? vr.z : 0.f;
                sr[k] += (kr.w == k) ? vr.w : 0.f;
            }
        }
#pragma unroll
        for (int k = 0; k < NCH; k++) {
#pragma unroll
            for (int off = 16; off; off >>= 1) {
                sg[k] += __shfl_xor_sync(0xffffffffu, sg[k], off);
                sr[k] += __shfl_xor_sync(0xffffffffu, sr[k], off);
            }
        }
        __shared__ float sm[16][2 * NCH];
        if (lane == 0) {
#pragma unroll
            for (int k = 0; k < NCH; k++) { sm[w][k] = sg[k]; sm[w][NCH + k] = sr[k]; }
        }
        __syncthreads();
        if (tid < 2 * NCH) {
            float t = 0.f;
#pragma unroll
            for (int i = 0; i < 16; i++) t += sm[i][tid];
            int k = tid % NCH;
            if (tid >= NCH) d_sum_r[(b * NCH + k) * NC + c] = t;
            else            d_sum_g[(b * NCH + k) * NC + c] = t;
        }
    }
}

// ---------------- kernel 3: normalize + transpose (16-pixel tiles, 576 blocks) ----------------
__global__ void __launch_bounds__(256) k_normalize(const float* __restrict__ gf, const float* __restrict__ rf) {
    __shared__ float tile[NC][17];
    int b = blockIdx.y;
    int p = blockIdx.z;
    int n0 = blockIdx.x * 16;
    int tid = threadIdx.x, lane = tid & 31, w = tid >> 5;
    const float* f    = (p == 0 ? gf : rf) + b * NC * NHW;
    const int*  cls   = (p == 0 ? d_cls_g : d_cls_r) + b * NHW;
    const float* sums = (p == 0 ? d_sum_g : d_sum_r) + b * NCH * NC;
    const int*  cnts  = (p == 0 ? d_cnt_g : d_cnt_r) + b * NCH;
    float* outp       = (p == 0 ? d_gn : d_rn) + b * NHW * NC;
    // fill: 256 rows x 4 float4 = 1024 vec loads, 4 per thread
#pragma unroll
    for (int it = 0; it < 4; it++) {
        int idx = tid + it * 256;
        int c = idx >> 2, q = idx & 3;
        float4 v = ((const float4*)(f + c * NHW + n0))[q];
        tile[c][q * 4 + 0] = v.x;
        tile[c][q * 4 + 1] = v.y;
        tile[c][q * 4 + 2] = v.z;
        tile[c][q * 4 + 3] = v.w;
    }
    __syncthreads();
#pragma unroll
    for (int q = 0; q < 2; q++) {
        int nn = w * 2 + q;
        int n = n0 + nn;
        int k = cls[n];
        float invc = 1.0f / fmaxf((float)cnts[k], 1.0f);
        const float* mk = sums + k * NC;
        float bar[8]; float ss = 0.f;
#pragma unroll
        for (int t = 0; t < 8; t++) {
            int c = lane + 32 * t;
            float v = tile[c][nn] - mk[c] * invc;
            bar[t] = v;
            ss += v * v;
        }
#pragma unroll
        for (int off = 16; off; off >>= 1) ss += __shfl_xor_sync(0xffffffffu, ss, off);
        float norm = sqrtf(ss);
        float inv = (norm > 0.f) ? (1.f / norm) : 1.f;
#pragma unroll
        for (int t = 0; t < 8; t++)
            outp[n * NC + lane + 32 * t] = bar[t] * inv;
    }
}

// ---------------- kernel 4: attention + fused merge (atomic ticket) ----------------
__global__ void __launch_bounds__(128, 3) k_attn(const float* __restrict__ img, float* __restrict__ out) {
    extern __shared__ __align__(16) float smem_dyn[];
    float* rn_s  = smem_dyn;                      // 2 * CBUF
    float* gn_s  = rn_s + 2 * CBUF;               // TI * GSTR
    float* img_s = gn_s + TI * GSTR;              // 2 * TJC * 4
    int*   s_pix = (int*)(img_s + 2 * TJC * 4);   // TI
    int*   s_last = s_pix + TI;                   // 1

    int yy = blockIdx.y;
    int k   = (yy % (NCH - 1)) + 1;
    int seg = yy / (NCH - 1);
    int b = blockIdx.z;
    int bk = b * NCH + k;
    int cg = d_cnt_g[bk], cr = d_cnt_r[bk];
    if (cg < 2 || cr < 2) return;

    int tid = threadIdx.x, lane = tid & 31, w = tid >> 5;   // w: 0..3
    int u = lane >> 3, v = lane & 7;                        // 2D lane tile
    const int* lg = d_list_g + bk * NHW;
    const int* lr = d_list_r + bk * NHW;
    const float4* gn4 = (const float4*)(d_gn + (size_t)b * NHW * NC);
    const float4* rn4 = (const float4*)(d_rn + (size_t)b * NHW * NC);
    const float* imgb = img + b * 3 * NHW;
    float4* partp = d_part + (size_t)bk * NHW * JS;

    uint32_t rn_su = (uint32_t)__cvta_generic_to_shared(rn_s);
    uint32_t gn_su = (uint32_t)__cvta_generic_to_shared(gn_s);
    int f_row  = tid >> 5;      // 0..3; rn fill rows f_row + 4*it
    int f_col4 = tid & 31;      // 0..31

    int nT   = (cr + TJC - 1) / TJC;
    int tBeg = (seg * nT) / JS, tEnd = ((seg + 1) * nT) / JS;
    int sBeg = 2 * tBeg, nSub = 2 * (tEnd - tBeg);   // nSub EVEN

    int I0 = w * 8 + u * 2;     // local i of this lane's first row

    for (int i_base = blockIdx.x * TI; i_base < cg; i_base += GX * TI) {
        __syncthreads();
        if (tid < TI) s_pix[tid] = lg[min(i_base + tid, cg - 1)];
        __syncthreads();    // s_pix visible

        // prologue: cp.async gn tile + rn sub-tile 0 + img tile, one commit group
        if (nSub > 0) {
            // gn tile: 2048 f4, 16 per thread, padded row stride 65 f4
#pragma unroll
            for (int it = 0; it < (TI * 64) / 128; it++) {
                int idx = tid + it * 128;
                int row = idx >> 6, col4 = idx & 63;
                uint32_t dst = gn_su + (uint32_t)((row * 65 + col4) * 16);
                CP_ASYNC16(dst, gn4 + (size_t)s_pix[row] * 64 + col4);
            }
            int j0 = tBeg * TJC;
#pragma unroll
            for (int it = 0; it < 8; it++) {
                int row = f_row + 4 * it;
                int jp = __ldg(lr + min(j0 + row, cr - 1));
                uint32_t dst = rn_su + (uint32_t)((row * CSTR + f_col4 * 4) * 4);
                CP_ASYNC16(dst, rn4 + (size_t)jp * 64 + f_col4);
            }
            CP_COMMIT();
            if (tid < TJC) {
                int jp = __ldg(lr + min(j0 + tid, cr - 1));
                float* ib = img_s + (tBeg & 1) * TJC * 4 + tid * 4;
                ib[0] = __ldg(imgb + 0 * NHW + jp);
                ib[1] = __ldg(imgb + 1 * NHW + jp);
                ib[2] = __ldg(imgb + 2 * NHW + jp);
            }
        }

        float sp[2] = {0.f, 0.f}, p0[2] = {0.f, 0.f}, p1[2] = {0.f, 0.f}, p2[2] = {0.f, 0.f};
        unsigned long long acc[2][4];

        for (int q = 0; q < nSub; q++) {
            int s = sBeg + q;
            int t = s >> 1, h = s & 1;
            int buf = q & 1;

            CP_WAIT0();
            __syncthreads();     // tile q (and gn at q=0) visible; buffer (1-buf) free

            if (q + 1 < nSub) {
                int s2 = s + 1;
                int t2 = s2 >> 1, h2 = s2 & 1;
                int j0n = t2 * TJC;
                uint32_t base = rn_su + (uint32_t)((1 - buf) * CBUF * 4);
#pragma unroll
                for (int it = 0; it < 8; it++) {
                    int row = f_row + 4 * it;
                    int jp = __ldg(lr + min(j0n + row, cr - 1));
                    uint32_t dst = base + (uint32_t)((row * CSTR + f_col4 * 4) * 4);
                    CP_ASYNC16(dst, rn4 + (size_t)jp * 64 + h2 * 32 + f_col4);
                }
                CP_COMMIT();
                if (h2 == 0 && tid < TJC) {
                    int jp = __ldg(lr + min(j0n + tid, cr - 1));
                    float* ib = img_s + (t2 & 1) * TJC * 4 + tid * 4;
                    ib[0] = __ldg(imgb + 0 * NHW + jp);
                    ib[1] = __ldg(imgb + 1 * NHW + jp);
                    ib[2] = __ldg(imgb + 2 * NHW + jp);
                }
            }

            if (h == 0) {
#pragma unroll
                for (int e = 0; e < 2; e++)
#pragma unroll
                    for (int jj = 0; jj < 4; jj++) acc[e][jj] = 0;
            }

            const ulonglong2* gp0 = (const ulonglong2*)(gn_s + (size_t)I0 * GSTR + h * CH);
            const ulonglong2* gp1 = (const ulonglong2*)(gn_s + (size_t)(I0 + 1) * GSTR + h * CH);
            const ulonglong2* rp0 = (const ulonglong2*)(rn_s + buf * CBUF + (v + 0) * CSTR);
            const ulonglong2* rp1 = (const ulonglong2*)(rn_s + buf * CBUF + (v + 8) * CSTR);
            const ulonglong2* rp2 = (const ulonglong2*)(rn_s + buf * CBUF + (v + 16) * CSTR);
            const ulonglong2* rp3 = (const ulonglong2*)(rn_s + buf * CBUF + (v + 24) * CSTR);
#pragma unroll
            for (int c4 = 0; c4 < CH / 4; c4++) {
                ulonglong2 g0 = gp0[c4], g1 = gp1[c4];
                ulonglong2 r0 = rp0[c4], r1 = rp1[c4], r2 = rp2[c4], r3 = rp3[c4];
                fma2(acc[0][0], r0.x, g0.x); fma2(acc[0][0], r0.y, g0.y);
                fma2(acc[0][1], r1.x, g0.x); fma2(acc[0][1], r1.y, g0.y);
                fma2(acc[0][2], r2.x, g0.x); fma2(acc[0][2], r2.y, g0.y);
                fma2(acc[0][3], r3.x, g0.x); fma2(acc[0][3], r3.y, g0.y);
                fma2(acc[1][0], r0.x, g1.x); fma2(acc[1][0], r0.y, g1.y);
                fma2(acc[1][1], r1.x, g1.x); fma2(acc[1][1], r1.y, g1.y);
                fma2(acc[1][2], r2.x, g1.x); fma2(acc[1][2], r2.y, g1.y);
                fma2(acc[1][3], r3.x, g1.x); fma2(acc[1][3], r3.y, g1.y);
            }

            if (h == 1) {
                int j0 = t * TJC;
                const float* ib = img_s + (t & 1) * TJC * 4;
#pragma unroll
                for (int jj = 0; jj < 4; jj++) {
                    int J = v + 8 * jj;
                    bool val = (j0 + J) < cr;
                    float i0v = ib[J * 4 + 0];
                    float i1v = ib[J * 4 + 1];
                    float i2v = ib[J * 4 + 2];
#pragma unroll
                    for (int e = 0; e < 2; e++) {
                        float d = hsum1(acc[e][jj]);
                        float ex = val ? __expf(d) : 0.f;   // logits in [-1,1]: no max tracking
                        sp[e] += ex;
                        p0[e] += ex * i0v;
                        p1[e] += ex * i1v;
                        p2[e] += ex * i2v;
                    }
                }
            }
        }

        // octet reduce (over v), write partials
#pragma unroll
        for (int e = 0; e < 2; e++) {
            float s_ = sp[e], x = p0[e], y = p1[e], z = p2[e];
#pragma unroll
            for (int off = 1; off <= 4; off <<= 1) {
                s_ += __shfl_xor_sync(0xffffffffu, s_, off);
                x  += __shfl_xor_sync(0xffffffffu, x, off);
                y  += __shfl_xor_sync(0xffffffffu, y, off);
                z  += __shfl_xor_sync(0xffffffffu, z, off);
            }
            int ig = i_base + I0 + e;
            if (v == 0 && ig < cg) {
                partp[ig * JS + seg] = make_float4(s_, x, y, z);
            }
        }
    }

    // ---- fused merge: last of GX*JS blocks for this (b,k) sums partials + scatters ----
    __threadfence();
    __syncthreads();
    if (tid == 0) {
        int old = atomicAdd(&d_ticket[bk], 1);
        *s_last = (old == GX * JS - 1) ? 1 : 0;
    }
    __syncthreads();
    if (*s_last) {
        __threadfence();
        for (int i = tid; i < cg; i += 128) {
            float s = 0.f, x = 0.f, y = 0.f, z = 0.f;
#pragma unroll
            for (int p = 0; p < JS; p++) {
                float4 P = partp[i * JS + p];
                s += P.x; x += P.y; y += P.z; z += P.w;
            }
            float inv = 1.0f / s;
            int pix = lg[i];
            out[b * 3 * NHW + 0 * NHW + pix] = x * inv;
            out[b * 3 * NHW + 1 * NHW + pix] = y * inv;
            out[b * 3 * NHW + 2 * NHW + pix] = z * inv;
        }
    }
}

// ---------------- launch ----------------
extern "C" void kernel_launch(void* const* d_in, const int* in_sizes, int n_in,
                              void* d_out, int out_size) {
    (void)in_sizes; (void)n_in; (void)out_size;
    const float* gf  = (const float*)d_in[0];
    const float* rf  = (const float*)d_in[1];
    const float* img = (const float*)d_in[2];
    const float* gl  = (const float*)d_in[3];
    const float* rl  = (const float*)d_in[4];
    float* out = (float*)d_out;

    cudaFuncSetAttribute(k_attn, cudaFuncAttributeMaxDynamicSharedMemorySize, ATTN_SMEM);

    k_classify<<<NB * NHW / 256, 256>>>(gl, rl, out);
    k_prep<<<NB * NCH + NB * NC, 512>>>(gf, rf);
    k_normalize<<<dim3(NHW / 16, NB, 2), 256>>>(gf, rf);
    k_attn<<<dim3(GX, (NCH - 1) * JS, NB), 128, ATTN_SMEM>>>(img, out);
}